// round 14
// baseline (speedup 1.0000x reference)
#include <cuda_runtime.h>
#include <cuda_bf16.h>
#include <cstdint>

#define BSZ 4096
#define DIM 1024
#define NSCALE 3
#define BM 128
#define BN 128
#define KSB 64              // bf16 K elements per stage (128 B of data per row)
#define KT16 (DIM / KSB)    // 16 stages
#define NBT (BSZ / BN)      // 32 column tiles
#define NST 3               // smem ring stages
#define NTHR 320            // 8 consumer warps + 2 producer warps
#define STAGE_B (BM * 128)                  // 16384 bytes per tile per stage (SW128 rows)
#define SMEM_DYN (2 * NST * STAGE_B + 1024) // + alignment slack

#define SW128(off) ((off) ^ (((off) >> 3) & 0x70))

// ---------------- scratch (static device globals; no allocation) ----------------
__device__ __nv_bfloat16 g_A[BSZ * DIM];
__device__ __nv_bfloat16 g_P[NSCALE][BSZ * DIM];
__device__ float g_invt[NSCALE][BSZ];
__device__ float g_part[NSCALE][NBT][4][BSZ];   // per-(coltile, warp-quarter) partials, 6 MB
__device__ float g_diag[NSCALE][BSZ];

struct Ptrs {
    const float* anchor;
    const int*   index;
    const int*   i2c[3];
    const float* cent[3];
    const float* dens[3];
};

// ---------------- PTX helpers ----------------
__device__ __forceinline__ uint32_t smem_u32(const void* p) {
    uint32_t a;
    asm("{ .reg .u64 t; cvta.to.shared.u64 t, %1; cvt.u32.u64 %0, t; }" : "=r"(a) : "l"(p));
    return a;
}
__device__ __forceinline__ void ldm_x4(uint32_t r[4], uint32_t addr) {
    asm volatile("ldmatrix.sync.aligned.m8n8.x4.shared.b16 {%0,%1,%2,%3}, [%4];\n"
                 : "=r"(r[0]), "=r"(r[1]), "=r"(r[2]), "=r"(r[3]) : "r"(addr));
}
__device__ __forceinline__ void mma16816(float c[4], const uint32_t a[4], const uint32_t b[2]) {
    asm volatile("mma.sync.aligned.m16n8k16.row.col.f32.bf16.bf16.f32 "
                 "{%0,%1,%2,%3}, {%4,%5,%6,%7}, {%8,%9}, {%0,%1,%2,%3};\n"
                 : "+f"(c[0]), "+f"(c[1]), "+f"(c[2]), "+f"(c[3])
                 : "r"(a[0]), "r"(a[1]), "r"(a[2]), "r"(a[3]), "r"(b[0]), "r"(b[1]));
}
__device__ __forceinline__ void cp16_s(uint32_t saddr, const void* gmem) {
    asm volatile("cp.async.cg.shared.global [%0], [%1], 16;\n" :: "r"(saddr), "l"(gmem));
}
__device__ __forceinline__ void mbar_init(uint32_t a, uint32_t cnt) {
    asm volatile("mbarrier.init.shared.b64 [%0], %1;" :: "r"(a), "r"(cnt) : "memory");
}
__device__ __forceinline__ void mbar_wait(uint32_t a, uint32_t parity) {
    uint32_t done = 0;
    while (!done)
        asm volatile("{ .reg .pred p; mbarrier.try_wait.parity.acquire.cta.shared::cta.b64 p, [%1], %2, 0x989680; selp.b32 %0, 1, 0, p; }"
                     : "=r"(done) : "r"(a), "r"(parity) : "memory");
}
__device__ __forceinline__ void mbar_arrive(uint32_t a) {
    asm volatile("mbarrier.arrive.shared::cta.b64 _, [%0];" :: "r"(a) : "memory");
}
// .noinc: the async arrive DECREMENTS the pending count (counts against init value).
// Default form is self-balancing (+1 at issue, -1 at completion) and would never
// complete a phase fed only by cp.async arrives -> round-12 hang.
__device__ __forceinline__ void cpasync_mbar_arrive_noinc(uint32_t a) {
    asm volatile("cp.async.mbarrier.arrive.noinc.shared::cta.b64 [%0];" :: "r"(a) : "memory");
}

// ---------------- prep: 2 rows per warp, normalize to bf16 ----------------
__global__ __launch_bounds__(256) void prep_kernel(Ptrs p) {
    int wbase = (blockIdx.x * 8 + (threadIdx.x >> 5)) * 2;
    int lane = threadIdx.x & 31;

    const float* src[2];
    __nv_bfloat16* dst[2];
    #pragma unroll
    for (int r = 0; r < 2; r++) {
        int w = wbase + r;
        if (w < BSZ) {
            src[r] = p.anchor + (size_t)w * DIM;
            dst[r] = g_A + (size_t)w * DIM;
        } else {
            int s = (w - BSZ) >> 12;
            int j = (w - BSZ) & (BSZ - 1);
            int cid = p.i2c[s][p.index[j]];
            src[r] = p.cent[s] + (size_t)cid * DIM;
            dst[r] = g_P[s] + (size_t)j * DIM;
            if (lane == (uint32_t)r) g_invt[s][j] = 1.0f / p.dens[s][cid];
        }
    }

    float4 x[2][8];
    #pragma unroll
    for (int k = 0; k < 8; k++) {
        x[0][k] = ((const float4*)src[0])[lane + 32 * k];
        x[1][k] = ((const float4*)src[1])[lane + 32 * k];
    }

    float ss0 = 0.f, ss1 = 0.f;
    #pragma unroll
    for (int k = 0; k < 8; k++) {
        ss0 += x[0][k].x * x[0][k].x + x[0][k].y * x[0][k].y + x[0][k].z * x[0][k].z + x[0][k].w * x[0][k].w;
        ss1 += x[1][k].x * x[1][k].x + x[1][k].y * x[1][k].y + x[1][k].z * x[1][k].z + x[1][k].w * x[1][k].w;
    }
    #pragma unroll
    for (int o = 16; o > 0; o >>= 1) {
        ss0 += __shfl_xor_sync(0xffffffffu, ss0, o);
        ss1 += __shfl_xor_sync(0xffffffffu, ss1, o);
    }
    float r0 = rsqrtf(fmaxf(ss0, 1e-24f));
    float r1 = rsqrtf(fmaxf(ss1, 1e-24f));

    __nv_bfloat162* d0 = (__nv_bfloat162*)dst[0];
    __nv_bfloat162* d1 = (__nv_bfloat162*)dst[1];
    #pragma unroll
    for (int k = 0; k < 8; k++) {
        d0[2 * (lane + 32 * k)]     = __floats2bfloat162_rn(x[0][k].x * r0, x[0][k].y * r0);
        d0[2 * (lane + 32 * k) + 1] = __floats2bfloat162_rn(x[0][k].z * r0, x[0][k].w * r0);
        d1[2 * (lane + 32 * k)]     = __floats2bfloat162_rn(x[1][k].x * r1, x[1][k].y * r1);
        d1[2 * (lane + 32 * k) + 1] = __floats2bfloat162_rn(x[1][k].z * r1, x[1][k].w * r1);
    }
}

// ---------------- warp-specialized GEMM (S = A @ P^T) + exp epilogue ----------------
__global__ __launch_bounds__(NTHR, 2) void gemm_kernel() {
    extern __shared__ char dynsmem[];
    const int scale = blockIdx.z;
    const int bm = blockIdx.y, bn = blockIdx.x;
    const int tid = threadIdx.x;
    const int lane = tid & 31;
    const int warp = tid >> 5;

    __shared__ float s_invt[BN + 2];
    __shared__ float s_invt0;
    __shared__ __align__(8) uint64_t s_full[NST];
    __shared__ __align__(8) uint64_t s_empty[NST];

    const uint32_t sAb = (smem_u32(dynsmem) + 1023u) & ~1023u;   // 1KB-align for SW128
    const uint32_t sBb = sAb + NST * STAGE_B;
    const uint32_t fullb = smem_u32(s_full);
    const uint32_t emptyb = smem_u32(s_empty);

    const __nv_bfloat16* gA = g_A + (size_t)(bm * BM) * DIM;
    const __nv_bfloat16* gB = g_P[scale] + (size_t)(bn * BN) * DIM;
    const float* invt = g_invt[scale];
    const int rowBase = bm * BM, colBase = bn * BN;

    if (tid <= BN) {
        int idx = colBase + tid;
        s_invt[tid] = invt[idx > BSZ - 1 ? BSZ - 1 : idx];
    }
    if (tid == 0) {
        s_invt0 = invt[0];
        #pragma unroll
        for (int s = 0; s < NST; s++) {
            mbar_init(fullb + 8 * s, 64);    // 64 producer lanes, .noinc async arrives
            mbar_init(emptyb + 8 * s, 8);    // 8 consumer warps, one elected lane each
        }
    }
    __syncthreads();   // the only CTA-wide barrier

    if (warp >= 8) {
        // ---------------- producer: warp 8 -> A tile, warp 9 -> B tile ----------------
        const __nv_bfloat16* src = (warp == 9) ? gB : gA;
        const uint32_t sb = (warp == 9) ? sBb : sAb;
        for (int kt = 0; kt < KT16; kt++) {
            const int buf = kt % NST;
            if (kt >= NST) mbar_wait(emptyb + 8 * buf, ((kt / NST) - 1) & 1);
            const __nv_bfloat16* ps = src + kt * KSB;
            const uint32_t sd = sb + buf * STAGE_B;
            #pragma unroll
            for (int i = 0; i < 32; i++) {
                int idx = lane + 32 * i;          // 1024 16B chunks per tile
                int row = idx >> 3, ch = idx & 7;
                cp16_s(sd + SW128((uint32_t)(row * 128 + ch * 16)),
                       ps + (size_t)row * DIM + ch * 8);
            }
            cpasync_mbar_arrive_noinc(fullb + 8 * buf);  // -1 when this lane's copies land
        }
        return;   // producers exit; no further CTA barriers exist
    }

    // ---------------- consumers: 8 warps, 64x32 tiles ----------------
    const int wm = warp >> 2;     // 0..1 : 64 rows each
    const int wn = warp & 3;      // 0..3 : 32 cols each

    float acc[4][4][4];
    #pragma unroll
    for (int a = 0; a < 4; a++)
        #pragma unroll
        for (int b = 0; b < 4; b++)
            #pragma unroll
            for (int c = 0; c < 4; c++) acc[a][b][c] = 0.f;

    const int aRow = wm * 64 + (lane & 15);
    const int aKo  = (lane & 16) ? 16 : 0;
    const int bRow = wn * 32 + (lane & 7) + ((lane & 16) ? 8 : 0);
    const int bKo  = (lane & 8) ? 16 : 0;

    for (int kt = 0; kt < KT16; kt++) {
        const int buf = kt % NST;
        mbar_wait(fullb + 8 * buf, (kt / NST) & 1);

        const uint32_t aT = sAb + buf * STAGE_B;
        const uint32_t bT = sBb + buf * STAGE_B;

        #pragma unroll
        for (int kk = 0; kk < KSB; kk += 16) {
            uint32_t af[4][4], bf[4][2];
            #pragma unroll
            for (int mb = 0; mb < 4; mb++) {
                uint32_t off = SW128((uint32_t)((aRow + mb * 16) * 128 + kk * 2 + aKo));
                ldm_x4(af[mb], aT + off);
            }
            #pragma unroll
            for (int nbp = 0; nbp < 2; nbp++) {
                uint32_t off = SW128((uint32_t)((bRow + nbp * 16) * 128 + kk * 2 + bKo));
                uint32_t t[4];
                ldm_x4(t, bT + off);
                bf[nbp * 2][0] = t[0]; bf[nbp * 2][1] = t[1];
                bf[nbp * 2 + 1][0] = t[2]; bf[nbp * 2 + 1][1] = t[3];
            }
            #pragma unroll
            for (int mb = 0; mb < 4; mb++)
                #pragma unroll
                for (int nb = 0; nb < 4; nb++)
                    mma16816(acc[mb][nb], af[mb], bf[nb]);
        }

        if (lane == 0) mbar_arrive(emptyb + 8 * buf);
    }

    // ---- epilogue: logits, exp, per-warp quarter-row sums straight to gmem ----
    const float invt0 = s_invt0;

    #pragma unroll
    for (int mb = 0; mb < 4; mb++) {
        #pragma unroll
        for (int h = 0; h < 2; h++) {
            int rl = wm * 64 + mb * 16 + (lane >> 2) + 8 * h;
            int gi = rowBase + rl;
            float rs = 0.f;
            #pragma unroll
            for (int nb = 0; nb < 4; nb++) {
                #pragma unroll
                for (int p = 0; p < 2; p++) {
                    int cl = wn * 32 + nb * 8 + 2 * (lane & 3) + p;
                    int gj = colBase + cl;
                    float sv = acc[mb][nb][h * 2 + p];
                    float l;
                    if (gj == gi) {
                        l = sv * invt0;              // positive column uses t[0]
                        g_diag[scale][gi] = l;
                    } else {
                        float w = (gj < gi) ? s_invt[cl + 1] : s_invt[cl];
                        l = sv * w;
                    }
                    rs += __expf(l);
                }
            }
            rs += __shfl_xor_sync(0xffffffffu, rs, 1);
            rs += __shfl_xor_sync(0xffffffffu, rs, 2);
            if ((lane & 3) == 0) g_part[scale][bn][wn][gi] = rs;   // written exactly once
        }
    }
}

// ---------------- finalize: lse + weighted combine ----------------
__global__ __launch_bounds__(256) void finalize_kernel(float* out) {
    int i = blockIdx.x * 256 + threadIdx.x;
    const float wgt[3] = {1.f / 27.f, 1.f / 9.f, 1.f / 3.f};
    float accum = 0.f;
    #pragma unroll
    for (int s = 0; s < NSCALE; s++) {
        float sum = 0.f;
        const float* base = &g_part[s][0][0][i];
        #pragma unroll 8
        for (int b = 0; b < NBT * 4; b++) sum += base[(size_t)b * BSZ];
        accum += wgt[s] * (logf(sum) - g_diag[s][i]);
    }
    out[i] = accum;
}

// ---------------- host entry ----------------
extern "C" void kernel_launch(void* const* d_in, const int* in_sizes, int n_in,
                              void* d_out, int out_size) {
    Ptrs p{};
    const long KsArr[3] = {10000, 20000, 50000};
    int ni = 0;
    for (int i = 0; i < n_in; i++) {
        long sz = in_sizes[i];
        if (sz == (long)BSZ * DIM) {
            p.anchor = (const float*)d_in[i];
        } else if (sz == BSZ) {
            p.index = (const int*)d_in[i];
        } else if (sz == 100000) {
            if (ni < 3) p.i2c[ni++] = (const int*)d_in[i];
        } else {
            for (int s = 0; s < 3; s++) {
                if (sz == KsArr[s]) p.dens[s] = (const float*)d_in[i];
                else if (sz == KsArr[s] * (long)DIM) p.cent[s] = (const float*)d_in[i];
            }
        }
    }

    cudaFuncSetAttribute(gemm_kernel, cudaFuncAttributeMaxDynamicSharedMemorySize, SMEM_DYN);

    prep_kernel<<<(4 * BSZ) / 16, 256>>>(p);
    gemm_kernel<<<dim3(NBT, BSZ / BM, NSCALE), NTHR, SMEM_DYN>>>();
    finalize_kernel<<<BSZ / 256, 256>>>((float*)d_out);
}